// round 1
// baseline (speedup 1.0000x reference)
#include <cuda_runtime.h>
#include <math.h>

#define CC 512
#define LV 196
#define BV 64
#define BT 32
#define NW 24
#define NK 98
#define KP 49
#define HH 102
#define OFFMASK (BV*BT)

// ---------------- device scratch (no allocation allowed) ----------------
__device__ float d_mu[BV*LV];
__device__ float d_rs[BV*LV];
__device__ float d_invn_img[BV*LV];
__device__ float d_imgglo[BV*CC];
__device__ float d_capglo[BT*CC];
__device__ float d_capinv[BT*NW];
__device__ float d_score[BT*BV*LV];
__device__ int   d_kidx[BT*BV*NK];
__device__ float d_wnon[BT*BV*LV];
__device__ float d_extra[BT*BV*CC];
__device__ float d_G1[CC*HH];
__device__ float d_cs[HH];
__device__ float d_bb[HH];
__device__ float d_wbuf[BT*BV*KP*NK];

// ---------------- row stats for img: mean, rsigma(LN), inv l2 norm ------
__global__ void kRowStats(const float* __restrict__ img) {
    int row = blockIdx.x;  // v*LV + l
    const float* p = img + (size_t)row * CC;
    float s = 0.f, ss = 0.f;
    for (int c = threadIdx.x; c < CC; c += 128) { float x = p[c]; s += x; ss += x * x; }
    __shared__ float r1[128], r2[128];
    r1[threadIdx.x] = s; r2[threadIdx.x] = ss; __syncthreads();
    for (int o = 64; o > 0; o >>= 1) {
        if (threadIdx.x < o) { r1[threadIdx.x] += r1[threadIdx.x+o]; r2[threadIdx.x] += r2[threadIdx.x+o]; }
        __syncthreads();
    }
    if (threadIdx.x == 0) {
        float sum = r1[0], sq = r2[0];
        float mu = sum / CC;
        float var = sq / CC - mu * mu;
        d_mu[row] = mu;
        d_rs[row] = rsqrtf(var + 1e-5f);
        d_invn_img[row] = 1.f / fmaxf(sqrtf(sq), 1e-12f);
    }
}

// ---------------- global (mean-pooled, l2-normalized) embeddings --------
__global__ void kGloImg(const float* __restrict__ img) {
    int b = blockIdx.x; int c = threadIdx.x;  // 512 threads
    float acc = 0.f;
    for (int l = 0; l < LV; l++) acc += img[((size_t)b*LV + l)*CC + c];
    acc /= (float)LV;
    __shared__ float red[512];
    red[c] = acc * acc; __syncthreads();
    for (int o = 256; o > 0; o >>= 1) { if (c < o) red[c] += red[c+o]; __syncthreads(); }
    float n = fmaxf(sqrtf(red[0]), 1e-12f);
    d_imgglo[b*CC + c] = acc / n;
}

__global__ void kGloCap(const float* __restrict__ cap) {
    int b = blockIdx.x; int c = threadIdx.x;
    float acc = 0.f;
    for (int l = 0; l < NW; l++) acc += cap[((size_t)b*NW + l)*CC + c];
    acc /= (float)NW;
    __shared__ float red[512];
    red[c] = acc * acc; __syncthreads();
    for (int o = 256; o > 0; o >>= 1) { if (c < o) red[c] += red[c+o]; __syncthreads(); }
    float n = fmaxf(sqrtf(red[0]), 1e-12f);
    d_capglo[b*CC + c] = acc / n;
}

__global__ void kCapRow(const float* __restrict__ cap) {
    int row = blockIdx.x;  // t*NW + w
    const float* p = cap + (size_t)row * CC;
    float ss = 0.f;
    for (int c = threadIdx.x; c < CC; c += 128) { float x = p[c]; ss += x * x; }
    __shared__ float red[128];
    red[threadIdx.x] = ss; __syncthreads();
    for (int o = 64; o > 0; o >>= 1) { if (threadIdx.x < o) red[threadIdx.x] += red[threadIdx.x+o]; __syncthreads(); }
    if (threadIdx.x == 0) d_capinv[row] = 1.f / fmaxf(sqrtf(red[0]), 1e-12f);
}

// ---------------- score[t,v,l] = self_attn + cross_attn -----------------
__global__ void kScore(const float* __restrict__ img) {
    int l = blockIdx.x, v = blockIdx.y;
    __shared__ float row[CC];
    const float* p = img + ((size_t)v*LV + l)*CC;
    for (int c = threadIdx.x; c < CC; c += 128) row[c] = p[c];
    __syncthreads();
    int lane = threadIdx.x & 31, wid = threadIdx.x >> 5;
    float inv = d_invn_img[v*LV + l];
    float sp = 0.f;
    #pragma unroll
    for (int e = 0; e < 16; e++) { int c = lane + 32*e; sp += row[c] * d_imgglo[v*CC + c]; }
    for (int o = 16; o; o >>= 1) sp += __shfl_xor_sync(0xffffffffu, sp, o);
    for (int t = wid; t < BT; t += 4) {
        float cp = 0.f;
        #pragma unroll
        for (int e = 0; e < 16; e++) { int c = lane + 32*e; cp += row[c] * d_capglo[t*CC + c]; }
        for (int o = 16; o; o >>= 1) cp += __shfl_xor_sync(0xffffffffu, cp, o);
        if (lane == 0) d_score[((size_t)t*BV + v)*LV + l] = inv * (sp + cp);
    }
}

// ---------------- exact top-K partition via stable rank -----------------
__global__ void kSelect(float* __restrict__ out) {
    int t = blockIdx.x, v = blockIdx.y;
    int tv = t*BV + v;
    __shared__ float s[LV];
    __shared__ float red[256];
    int tid = threadIdx.x;
    if (tid < LV) s[tid] = d_score[(size_t)tv*LV + tid];
    __syncthreads();
    int cnt = 0; float sl = 0.f; bool keep = false;
    if (tid < LV) {
        sl = s[tid];
        for (int j = 0; j < LV; j++) {
            float sj = s[j];
            cnt += (sj > sl) || (sj == sl && j < tid);
        }
        keep = cnt < NK;
        out[OFFMASK + (size_t)tv*LV + tid] = keep ? 1.f : 0.f;
        if (keep) d_kidx[tv*NK + cnt] = tid;
    }
    // softmax over non-kept scores (order-invariant)
    red[tid] = (tid < LV && !keep) ? sl : -INFINITY;
    __syncthreads();
    for (int o = 128; o > 0; o >>= 1) { if (tid < o) red[tid] = fmaxf(red[tid], red[tid+o]); __syncthreads(); }
    float m = red[0];
    __syncthreads();
    float ev = (tid < LV && !keep) ? expf(sl - m) : 0.f;
    red[tid] = ev;
    __syncthreads();
    for (int o = 128; o > 0; o >>= 1) { if (tid < o) red[tid] += red[tid+o]; __syncthreads(); }
    float Z = red[0];
    if (tid < LV) d_wnon[(size_t)tv*LV + tid] = keep ? 0.f : ev / Z;
}

// ---------------- extra token: softmax-weighted sum of non-kept ---------
__global__ void kExtra(const float* __restrict__ img) {
    int t = blockIdx.x, v = blockIdx.y; int tv = t*BV + v;
    __shared__ float wn[LV];
    int tid = threadIdx.x;
    if (tid < LV) wn[tid] = d_wnon[(size_t)tv*LV + tid];
    __syncthreads();
    for (int c = tid; c < CC; c += 256) {
        float acc = 0.f;
        for (int l = 0; l < LV; l++) acc += wn[l] * img[((size_t)v*LV + l)*CC + c];
        d_extra[(size_t)tv*CC + c] = acc;
    }
}

// ---------------- fold gamma/beta into W1 -------------------------------
__global__ void kPrepG1(const float* __restrict__ W1, const float* __restrict__ gamma) {
    int idx = blockIdx.x*256 + threadIdx.x;
    if (idx < CC*HH) { int c = idx / HH; d_G1[idx] = gamma[c] * W1[idx]; }
}

__global__ void kPrepCol(const float* __restrict__ W1, const float* __restrict__ beta,
                         const float* __restrict__ b1) {
    int h = blockIdx.x;
    float s1 = 0.f, s2 = 0.f;
    for (int c = threadIdx.x; c < CC; c += 128) {
        s1 += d_G1[c*HH + h];
        s2 += beta[c] * W1[c*HH + h];
    }
    __shared__ float r1[128], r2[128];
    r1[threadIdx.x] = s1; r2[threadIdx.x] = s2; __syncthreads();
    for (int o = 64; o > 0; o >>= 1) {
        if (threadIdx.x < o) { r1[threadIdx.x] += r1[threadIdx.x+o]; r2[threadIdx.x] += r2[threadIdx.x+o]; }
        __syncthreads();
    }
    if (threadIdx.x == 0) { d_cs[h] = r1[0]; d_bb[h] = r2[0] + b1[h]; }
}

// ---------------- E1: LN-folded MLP + softmax -> aggregation weights ----
// per (t,v): h = gelu(xn@G1 + bb), logits = scale*(h@W2+b2), softmax over k
#define E1_FLOATS (6370 + 6656 + 10192 + 5304 + 4900 + 102 + 102 + 98 + 98 + 49 + 1)
#define SMEM_E1 (E1_FLOATS*4 + 98*4)

__global__ void kE1(const float* __restrict__ img, const float* __restrict__ W2,
                    const float* __restrict__ b2, const float* __restrict__ scale) {
    extern __shared__ float sm[];
    float* As  = sm;               // 98 x 65 (padded)
    float* Gs  = As + 6370;        // 64 x 104
    float* Hs  = Gs + 6656;        // 98 x 104
    float* W2s = Hs + 10192;       // 102 x 52
    float* Lg  = W2s + 5304;       // 49 x 100
    float* css = Lg + 4900;        // 102
    float* bbs = css + 102;        // 102
    float* mus = bbs + 102;        // 98
    float* rss = mus + 98;         // 98
    float* b2s = rss + 98;         // 49
    float* ssc = b2s + 49;         // 1
    int*   kix = (int*)(ssc + 1);  // 98

    int t = blockIdx.x, v = blockIdx.y; int tv = t*BV + v;
    int tid = threadIdx.x; int tx = tid & 15, ty = tid >> 4;

    if (tid < NK) {
        int k = d_kidx[tv*NK + tid];
        kix[tid] = k;
        mus[tid] = d_mu[v*LV + k];
        rss[tid] = d_rs[v*LV + k];
    }
    if (tid < HH) { css[tid] = d_cs[tid]; bbs[tid] = d_bb[tid]; }
    if (tid < KP) b2s[tid] = b2[tid];
    if (tid == 0) ssc[0] = scale[0];
    __syncthreads();

    float acc[7][7];
    #pragma unroll
    for (int i = 0; i < 7; i++)
        #pragma unroll
        for (int j = 0; j < 7; j++) acc[i][j] = 0.f;

    for (int k0 = 0; k0 < CC; k0 += 64) {
        for (int idx = tid; idx < NK*64; idx += 256) {
            int r = idx >> 6, kk = idx & 63;
            As[r*65 + kk] = img[((size_t)v*LV + kix[r])*CC + k0 + kk];
        }
        for (int idx = tid; idx < 64*HH; idx += 256) {
            int rr = idx / HH, c = idx % HH;
            Gs[rr*104 + c] = d_G1[(k0 + rr)*HH + c];
        }
        __syncthreads();
        #pragma unroll 4
        for (int kk = 0; kk < 64; kk++) {
            float a[7], b[7];
            #pragma unroll
            for (int i = 0; i < 7; i++) { int r = ty + 16*i; if (r > 97) r = 97; a[i] = As[r*65 + kk]; }
            #pragma unroll
            for (int j = 0; j < 7; j++) { int c = tx + 16*j; if (c > 101) c = 101; b[j] = Gs[kk*104 + c]; }
            #pragma unroll
            for (int i = 0; i < 7; i++)
                #pragma unroll
                for (int j = 0; j < 7; j++) acc[i][j] += a[i] * b[j];
        }
        __syncthreads();
    }

    // epilogue: LN fold + exact gelu -> Hs
    #pragma unroll
    for (int i = 0; i < 7; i++) {
        int r = ty + 16*i;
        if (r < NK) {
            float mu = mus[r], rsg = rss[r];
            #pragma unroll
            for (int j = 0; j < 7; j++) {
                int c = tx + 16*j;
                if (c < HH) {
                    float x = rsg * (acc[i][j] - mu * css[c]) + bbs[c];
                    Hs[r*104 + c] = 0.5f * x * (1.f + erff(x * 0.70710678118654752f));
                }
            }
        }
    }
    for (int idx = tid; idx < HH*KP; idx += 256) {
        int h = idx / KP, p = idx % KP;
        W2s[h*52 + p] = W2[idx];
    }
    __syncthreads();

    float sc = ssc[0];
    for (int idx = tid; idx < NK*KP; idx += 256) {
        int k = idx / KP, p = idx % KP;
        float a2 = b2s[p];
        for (int h = 0; h < HH; h++) a2 += Hs[k*104 + h] * W2s[h*52 + p];
        Lg[p*100 + k] = sc * a2;
    }
    __syncthreads();

    if (tid < KP) {
        float m = -INFINITY;
        for (int k = 0; k < NK; k++) m = fmaxf(m, Lg[tid*100 + k]);
        float Z = 0.f;
        for (int k = 0; k < NK; k++) { float e = expf(Lg[tid*100 + k] - m); Lg[tid*100 + k] = e; Z += e; }
        float iz = 1.f / Z;
        for (int k = 0; k < NK; k++) Lg[tid*100 + k] *= iz;
    }
    __syncthreads();
    for (int idx = tid; idx < KP*NK; idx += 256)
        d_wbuf[(size_t)tv*KP*NK + idx] = Lg[(idx/NK)*100 + (idx % NK)];
}

// ---------------- E2: aggr, sims, attn, ctx, word_sim -> sim ------------
#define E2_FLOATS (26000 + 12740 + 4900 + 1248 + 52 + 24)
#define SMEM_E2 (E2_FLOATS*4 + 98*4)

__global__ void kE2(const float* __restrict__ img, const float* __restrict__ cap,
                    float* __restrict__ out) {
    extern __shared__ float sm[];
    float* KT   = sm;              // 50 x 520 (49 aggr rows + extra row)
    float* SC   = KT + 26000;      // 98 x 130  (reused as CAP: 24 x 516)
    float* WW   = SC + 12740;      // 49 x 100
    float* ATT  = WW + 4900;       // 24 x 52
    float* invn = ATT + 1248;      // 52
    float* wsm  = invn + 52;       // 24
    int*   kix  = (int*)(wsm + 24);// 98

    int t = blockIdx.x, v = blockIdx.y; int tv = t*BV + v;
    int tid = threadIdx.x; int tx = tid & 15, ty = tid >> 4;
    int lane = tid & 31, wid = tid >> 5;

    if (tid < NK) kix[tid] = d_kidx[tv*NK + tid];
    for (int idx = tid; idx < KP*NK; idx += 256)
        WW[(idx/NK)*100 + (idx % NK)] = d_wbuf[(size_t)tv*KP*NK + idx];
    for (int c = tid; c < CC; c += 256) KT[49*520 + c] = d_extra[(size_t)tv*CC + c];
    __syncthreads();

    // aggr[p, c] = sum_k w[p,k] * S[k,c], tiled over c in chunks of 128
    for (int c0 = 0; c0 < CC; c0 += 128) {
        for (int idx = tid; idx < NK*128; idx += 256) {
            int r = idx >> 7, cc = idx & 127;
            SC[r*130 + cc] = img[((size_t)v*LV + kix[r])*CC + c0 + cc];
        }
        __syncthreads();
        float acc[4][8];
        #pragma unroll
        for (int i = 0; i < 4; i++)
            #pragma unroll
            for (int j = 0; j < 8; j++) acc[i][j] = 0.f;
        #pragma unroll 2
        for (int k = 0; k < NK; k++) {
            float wv[4], sv[8];
            #pragma unroll
            for (int i = 0; i < 4; i++) { int p = ty + 16*i; if (p > 48) p = 48; wv[i] = WW[p*100 + k]; }
            #pragma unroll
            for (int j = 0; j < 8; j++) sv[j] = SC[k*130 + tx + 16*j];
            #pragma unroll
            for (int i = 0; i < 4; i++)
                #pragma unroll
                for (int j = 0; j < 8; j++) acc[i][j] += wv[i] * sv[j];
        }
        #pragma unroll
        for (int i = 0; i < 4; i++) {
            int p = ty + 16*i;
            if (p < KP) {
                #pragma unroll
                for (int j = 0; j < 8; j++) KT[p*520 + c0 + tx + 16*j] = acc[i][j];
            }
        }
        __syncthreads();
    }

    // inverse l2 norms of all 50 keep_tokens
    for (int p = wid; p < KP + 1; p += 8) {
        float ss = 0.f;
        #pragma unroll
        for (int e = 0; e < 16; e++) { float x = KT[p*520 + lane + 32*e]; ss += x * x; }
        for (int o = 16; o; o >>= 1) ss += __shfl_xor_sync(0xffffffffu, ss, o);
        if (lane == 0) invn[p] = 1.f / fmaxf(sqrtf(ss), 1e-12f);
    }
    __syncthreads();

    // load normalized caption words into SC region
    for (int idx = tid; idx < NW*CC; idx += 256) {
        int w = idx >> 9, c = idx & 511;
        SC[w*516 + c] = cap[((size_t)t*NW + w)*CC + c] * d_capinv[t*NW + w];
    }
    __syncthreads();

    // per-word: sims -> softmax -> ctx -> word_sim (one warp per word)
    for (int w = wid; w < NW; w += 8) {
        for (int p = 0; p < KP + 1; p++) {
            float d = 0.f;
            #pragma unroll
            for (int e = 0; e < 16; e++) d += SC[w*516 + lane + 32*e] * KT[p*520 + lane + 32*e];
            for (int o = 16; o; o >>= 1) d += __shfl_xor_sync(0xffffffffu, d, o);
            if (lane == 0) ATT[w*52 + p] = 4.f * invn[p] * d;
        }
        __syncwarp();
        float a0 = (lane < 50) ? ATT[w*52 + lane] : -INFINITY;
        float a1 = (lane + 32 < 50) ? ATT[w*52 + lane + 32] : -INFINITY;
        float m = fmaxf(a0, a1);
        for (int o = 16; o; o >>= 1) m = fmaxf(m, __shfl_xor_sync(0xffffffffu, m, o));
        float e0 = (lane < 50) ? expf(a0 - m) : 0.f;
        float e1 = (lane + 32 < 50) ? expf(a1 - m) : 0.f;
        float Z = e0 + e1;
        for (int o = 16; o; o >>= 1) Z += __shfl_xor_sync(0xffffffffu, Z, o);
        float iz = 1.f / Z;
        if (lane < 50) ATT[w*52 + lane] = e0 * iz;
        if (lane + 32 < 50) ATT[w*52 + lane + 32] = e1 * iz;
        __syncwarp();
        float cx[16];
        #pragma unroll
        for (int e = 0; e < 16; e++) cx[e] = 0.f;
        for (int p = 0; p < KP + 1; p++) {
            float a = ATT[w*52 + p] * invn[p];
            #pragma unroll
            for (int e = 0; e < 16; e++) cx[e] += a * KT[p*520 + lane + 32*e];
        }
        float ss = 0.f, dt = 0.f;
        #pragma unroll
        for (int e = 0; e < 16; e++) {
            ss += cx[e] * cx[e];
            dt += cx[e] * SC[w*516 + lane + 32*e];
        }
        for (int o = 16; o; o >>= 1) {
            ss += __shfl_xor_sync(0xffffffffu, ss, o);
            dt += __shfl_xor_sync(0xffffffffu, dt, o);
        }
        if (lane == 0) wsm[w] = dt / fmaxf(sqrtf(ss), 1e-12f);
    }
    __syncthreads();
    if (tid == 0) {
        float s = 0.f;
        for (int w = 0; w < NW; w++) s += wsm[w];
        out[v*BT + t] = s / (float)NW;   // improve_sims = sim.T
    }
}

// ------------------------------ launch ----------------------------------
extern "C" void kernel_launch(void* const* d_in, const int* in_sizes, int n_in,
                              void* d_out, int out_size) {
    const float* img   = (const float*)d_in[0];
    const float* cap   = (const float*)d_in[1];
    // d_in[2] = cap_lens (unused by reference math)
    const float* gamma = (const float*)d_in[3];
    const float* beta  = (const float*)d_in[4];
    const float* W1    = (const float*)d_in[5];
    const float* b1    = (const float*)d_in[6];
    const float* W2    = (const float*)d_in[7];
    const float* b2    = (const float*)d_in[8];
    const float* scale = (const float*)d_in[9];
    float* out = (float*)d_out;

    kRowStats<<<BV*LV, 128>>>(img);
    kGloImg<<<BV, 512>>>(img);
    kGloCap<<<BT, 512>>>(cap);
    kCapRow<<<BT*NW, 128>>>(cap);
    kScore<<<dim3(LV, BV), 128>>>(img);
    kSelect<<<dim3(BT, BV), 256>>>(out);
    kExtra<<<dim3(BT, BV), 256>>>(img);
    kPrepG1<<<(CC*HH + 255)/256, 256>>>(W1, gamma);
    kPrepCol<<<HH, 128>>>(W1, beta, b1);

    cudaFuncSetAttribute(kE1, cudaFuncAttributeMaxDynamicSharedMemorySize, SMEM_E1);
    kE1<<<dim3(BT, BV), 256, SMEM_E1>>>(img, W2, b2, scale);

    cudaFuncSetAttribute(kE2, cudaFuncAttributeMaxDynamicSharedMemorySize, SMEM_E2);
    kE2<<<dim3(BT, BV), 256, SMEM_E2>>>(img, cap, out);
}

// round 2
// speedup vs baseline: 2.2023x; 2.2023x over previous
#include <cuda_runtime.h>
#include <math.h>

#define CC 512
#define LV 196
#define BV 64
#define BT 32
#define NW 24
#define NK 98
#define KP 49
#define HH 102
#define OFFMASK (BV*BT)

// ---------------- device scratch (no allocation allowed) ----------------
__device__ float d_mu[BV*LV];
__device__ float d_rs[BV*LV];
__device__ float d_invn_img[BV*LV];
__device__ float d_imgglo[BV*CC];
__device__ float d_capglo[BT*CC];
__device__ float d_capinv[BT*NW];
__device__ float d_score[BT*BV*LV];
__device__ int   d_kidx[BT*BV*NK];
__device__ float d_wnon[BT*BV*LV];
__device__ float d_extra[BT*BV*CC];
__device__ float d_G1[CC*HH];
__device__ float d_cs[HH];
__device__ float d_bb[HH];
__device__ float d_L[BV*LV*KP];   // precomputed (scaled) logits per (v,l,p)

// ---------------- row stats for img: mean, rsigma(LN), inv l2 norm ------
__global__ void kRowStats(const float* __restrict__ img) {
    int row = blockIdx.x;  // v*LV + l
    const float* p = img + (size_t)row * CC;
    float s = 0.f, ss = 0.f;
    for (int c = threadIdx.x; c < CC; c += 128) { float x = p[c]; s += x; ss += x * x; }
    __shared__ float r1[128], r2[128];
    r1[threadIdx.x] = s; r2[threadIdx.x] = ss; __syncthreads();
    for (int o = 64; o > 0; o >>= 1) {
        if (threadIdx.x < o) { r1[threadIdx.x] += r1[threadIdx.x+o]; r2[threadIdx.x] += r2[threadIdx.x+o]; }
        __syncthreads();
    }
    if (threadIdx.x == 0) {
        float sum = r1[0], sq = r2[0];
        float mu = sum / CC;
        float var = sq / CC - mu * mu;
        d_mu[row] = mu;
        d_rs[row] = rsqrtf(var + 1e-5f);
        d_invn_img[row] = 1.f / fmaxf(sqrtf(sq), 1e-12f);
    }
}

// ---------------- global (mean-pooled, l2-normalized) embeddings --------
__global__ void kGloImg(const float* __restrict__ img) {
    int b = blockIdx.x; int c = threadIdx.x;  // 512 threads
    float acc = 0.f;
    for (int l = 0; l < LV; l++) acc += img[((size_t)b*LV + l)*CC + c];
    acc /= (float)LV;
    __shared__ float red[512];
    red[c] = acc * acc; __syncthreads();
    for (int o = 256; o > 0; o >>= 1) { if (c < o) red[c] += red[c+o]; __syncthreads(); }
    float n = fmaxf(sqrtf(red[0]), 1e-12f);
    d_imgglo[b*CC + c] = acc / n;
}

__global__ void kGloCap(const float* __restrict__ cap) {
    int b = blockIdx.x; int c = threadIdx.x;
    float acc = 0.f;
    for (int l = 0; l < NW; l++) acc += cap[((size_t)b*NW + l)*CC + c];
    acc /= (float)NW;
    __shared__ float red[512];
    red[c] = acc * acc; __syncthreads();
    for (int o = 256; o > 0; o >>= 1) { if (c < o) red[c] += red[c+o]; __syncthreads(); }
    float n = fmaxf(sqrtf(red[0]), 1e-12f);
    d_capglo[b*CC + c] = acc / n;
}

__global__ void kCapRow(const float* __restrict__ cap) {
    int row = blockIdx.x;  // t*NW + w
    const float* p = cap + (size_t)row * CC;
    float ss = 0.f;
    for (int c = threadIdx.x; c < CC; c += 128) { float x = p[c]; ss += x * x; }
    __shared__ float red[128];
    red[threadIdx.x] = ss; __syncthreads();
    for (int o = 64; o > 0; o >>= 1) { if (threadIdx.x < o) red[threadIdx.x] += red[threadIdx.x+o]; __syncthreads(); }
    if (threadIdx.x == 0) d_capinv[row] = 1.f / fmaxf(sqrtf(red[0]), 1e-12f);
}

// ---------------- score[t,v,l] = self_attn + cross_attn -----------------
__global__ void kScore(const float* __restrict__ img) {
    int l = blockIdx.x, v = blockIdx.y;
    __shared__ float row[CC];
    const float* p = img + ((size_t)v*LV + l)*CC;
    for (int c = threadIdx.x; c < CC; c += 128) row[c] = p[c];
    __syncthreads();
    int lane = threadIdx.x & 31, wid = threadIdx.x >> 5;
    float inv = d_invn_img[v*LV + l];
    float sp = 0.f;
    #pragma unroll
    for (int e = 0; e < 16; e++) { int c = lane + 32*e; sp += row[c] * d_imgglo[v*CC + c]; }
    for (int o = 16; o; o >>= 1) sp += __shfl_xor_sync(0xffffffffu, sp, o);
    for (int t = wid; t < BT; t += 4) {
        float cp = 0.f;
        #pragma unroll
        for (int e = 0; e < 16; e++) { int c = lane + 32*e; cp += row[c] * d_capglo[t*CC + c]; }
        for (int o = 16; o; o >>= 1) cp += __shfl_xor_sync(0xffffffffu, cp, o);
        if (lane == 0) d_score[((size_t)t*BV + v)*LV + l] = inv * (sp + cp);
    }
}

// ---------------- exact top-K partition via stable rank -----------------
__global__ void kSelect(float* __restrict__ out) {
    int t = blockIdx.x, v = blockIdx.y;
    int tv = t*BV + v;
    __shared__ float s[LV];
    __shared__ float red[256];
    int tid = threadIdx.x;
    if (tid < LV) s[tid] = d_score[(size_t)tv*LV + tid];
    __syncthreads();
    int cnt = 0; float sl = 0.f; bool keep = false;
    if (tid < LV) {
        sl = s[tid];
        for (int j = 0; j < LV; j++) {
            float sj = s[j];
            cnt += (sj > sl) || (sj == sl && j < tid);
        }
        keep = cnt < NK;
        out[OFFMASK + (size_t)tv*LV + tid] = keep ? 1.f : 0.f;
        if (keep) d_kidx[tv*NK + cnt] = tid;
    }
    // softmax over non-kept scores (order-invariant)
    red[tid] = (tid < LV && !keep) ? sl : -INFINITY;
    __syncthreads();
    for (int o = 128; o > 0; o >>= 1) { if (tid < o) red[tid] = fmaxf(red[tid], red[tid+o]); __syncthreads(); }
    float m = red[0];
    __syncthreads();
    float ev = (tid < LV && !keep) ? expf(sl - m) : 0.f;
    red[tid] = ev;
    __syncthreads();
    for (int o = 128; o > 0; o >>= 1) { if (tid < o) red[tid] += red[tid+o]; __syncthreads(); }
    float Z = red[0];
    if (tid < LV) d_wnon[(size_t)tv*LV + tid] = keep ? 0.f : ev / Z;
}

// ---------------- extra tokens: one block per v, all 32 t at once -------
__global__ void kExtra(const float* __restrict__ img) {
    int v = blockIdx.x;
    __shared__ float wn[BT*LV];
    int tid = threadIdx.x;
    for (int idx = tid; idx < BT*LV; idx += 256)
        wn[idx] = d_wnon[((size_t)(idx/LV)*BV + v)*LV + (idx % LV)];
    __syncthreads();
    #pragma unroll
    for (int half = 0; half < 2; half++) {
        int c = tid + 256*half;
        float acc[BT];
        #pragma unroll
        for (int t = 0; t < BT; t++) acc[t] = 0.f;
        for (int l = 0; l < LV; l++) {
            float x = img[((size_t)v*LV + l)*CC + c];
            #pragma unroll
            for (int t = 0; t < BT; t++) acc[t] += wn[t*LV + l] * x;
        }
        #pragma unroll
        for (int t = 0; t < BT; t++) d_extra[((size_t)t*BV + v)*CC + c] = acc[t];
    }
}

// ---------------- fold gamma/beta into W1 -------------------------------
__global__ void kPrepG1(const float* __restrict__ W1, const float* __restrict__ gamma) {
    int idx = blockIdx.x*256 + threadIdx.x;
    if (idx < CC*HH) { int c = idx / HH; d_G1[idx] = gamma[c] * W1[idx]; }
}

__global__ void kPrepCol(const float* __restrict__ W1, const float* __restrict__ beta,
                         const float* __restrict__ b1) {
    int h = blockIdx.x;
    float s1 = 0.f, s2 = 0.f;
    for (int c = threadIdx.x; c < CC; c += 128) {
        s1 += d_G1[c*HH + h];
        s2 += beta[c] * W1[c*HH + h];
    }
    __shared__ float r1[128], r2[128];
    r1[threadIdx.x] = s1; r2[threadIdx.x] = s2; __syncthreads();
    for (int o = 64; o > 0; o >>= 1) {
        if (threadIdx.x < o) { r1[threadIdx.x] += r1[threadIdx.x+o]; r2[threadIdx.x] += r2[threadIdx.x+o]; }
        __syncthreads();
    }
    if (threadIdx.x == 0) { d_cs[h] = r1[0]; d_bb[h] = r2[0] + b1[h]; }
}

// ---------------- kHL: per (v, row-half) LN-folded MLP -> logits --------
// L[v,l,p] = scale * (gelu(rs*(row@G1 - mu*cs) + bb) @ W2 + b2)
// grid (BV, 2): each block handles 98 contiguous rows of img[v].
#define HL_FLOATS (6664 + 6656 + 10192 + 5304 + 102 + 102 + 98 + 98 + 49 + 1)
#define SMEM_HL (HL_FLOATS*4)

__global__ void kHL(const float* __restrict__ img, const float* __restrict__ W2,
                    const float* __restrict__ b2, const float* __restrict__ scale) {
    extern __shared__ float sm[];
    float* As  = sm;               // 98 x 68 (float4-aligned stride)
    float* Gs  = As + 6664;        // 64 x 104
    float* Hs  = Gs + 6656;        // 98 x 104
    float* W2s = Hs + 10192;       // 102 x 52
    float* css = W2s + 5304;       // 102
    float* bbs = css + 102;        // 102
    float* mus = bbs + 102;        // 98
    float* rss = mus + 98;         // 98
    float* b2s = rss + 98;         // 49
    float* ssc = b2s + 49;         // 1

    int v = blockIdx.x, l0 = blockIdx.y * NK;
    int tid = threadIdx.x; int tx = tid & 15, ty = tid >> 4;

    if (tid < NK) {
        int row = v*LV + l0 + tid;
        mus[tid] = d_mu[row];
        rss[tid] = d_rs[row];
    }
    if (tid < HH) { css[tid] = d_cs[tid]; bbs[tid] = d_bb[tid]; }
    if (tid < KP) b2s[tid] = b2[tid];
    if (tid == 0) ssc[0] = scale[0];
    __syncthreads();

    float acc[7][7];
    #pragma unroll
    for (int i = 0; i < 7; i++)
        #pragma unroll
        for (int j = 0; j < 7; j++) acc[i][j] = 0.f;

    for (int k0 = 0; k0 < CC; k0 += 64) {
        for (int idx = tid; idx < NK*16; idx += 256) {
            int r = idx >> 4, q = (idx & 15) << 2;
            *(float4*)&As[r*68 + q] =
                *(const float4*)&img[((size_t)v*LV + l0 + r)*CC + k0 + q];
        }
        for (int idx = tid; idx < 64*HH; idx += 256) {
            int rr = idx / HH, c = idx % HH;
            Gs[rr*104 + c] = d_G1[(k0 + rr)*HH + c];
        }
        __syncthreads();
        #pragma unroll 4
        for (int kk = 0; kk < 64; kk++) {
            float a[7], b[7];
            #pragma unroll
            for (int i = 0; i < 7; i++) { int r = ty + 16*i; if (r > 97) r = 97; a[i] = As[r*68 + kk]; }
            #pragma unroll
            for (int j = 0; j < 7; j++) { int c = tx + 16*j; if (c > 101) c = 101; b[j] = Gs[kk*104 + c]; }
            #pragma unroll
            for (int i = 0; i < 7; i++)
                #pragma unroll
                for (int j = 0; j < 7; j++) acc[i][j] += a[i] * b[j];
        }
        __syncthreads();
    }

    // epilogue: LN fold + exact gelu -> Hs
    #pragma unroll
    for (int i = 0; i < 7; i++) {
        int r = ty + 16*i;
        if (r < NK) {
            float mu = mus[r], rsg = rss[r];
            #pragma unroll
            for (int j = 0; j < 7; j++) {
                int c = tx + 16*j;
                if (c < HH) {
                    float x = rsg * (acc[i][j] - mu * css[c]) + bbs[c];
                    Hs[r*104 + c] = 0.5f * x * (1.f + erff(x * 0.70710678118654752f));
                }
            }
        }
    }
    for (int idx = tid; idx < HH*KP; idx += 256) {
        int h = idx / KP, p = idx % KP;
        W2s[h*52 + p] = W2[idx];
    }
    __syncthreads();

    float sc = ssc[0];
    for (int idx = tid; idx < NK*KP; idx += 256) {
        int r = idx / KP, p = idx % KP;
        float a2 = b2s[p];
        for (int h = 0; h < HH; h++) a2 += Hs[r*104 + h] * W2s[h*52 + p];
        d_L[((size_t)v*LV + l0 + r)*KP + p] = sc * a2;
    }
}

// ---------------- E2: gather logits, softmax, aggr, sims, ctx -> sim ----
#define E2_FLOATS (26000 + 12936 + 4900 + 1248 + 52 + 24)
#define SMEM_E2 (E2_FLOATS*4 + 98*4)

__global__ void kE2(const float* __restrict__ img, const float* __restrict__ cap,
                    float* __restrict__ out) {
    extern __shared__ float sm[];
    float* KT   = sm;              // 50 x 520 (49 aggr rows + extra row)
    float* SC   = KT + 26000;      // 98 x 132  (reused as CAP: 24 x 516)
    float* WW   = SC + 12936;      // 49 x 100  (logits -> softmax weights)
    float* ATT  = WW + 4900;       // 24 x 52
    float* invn = ATT + 1248;      // 52
    float* wsm  = invn + 52;       // 24
    int*   kix  = (int*)(wsm + 24);// 98

    int t = blockIdx.x, v = blockIdx.y; int tv = t*BV + v;
    int tid = threadIdx.x; int tx = tid & 15, ty = tid >> 4;
    int lane = tid & 31, wid = tid >> 5;

    if (tid < NK) kix[tid] = d_kidx[tv*NK + tid];
    for (int c = tid; c < CC; c += 256) KT[49*520 + c] = d_extra[(size_t)tv*CC + c];
    __syncthreads();

    // gather precomputed logits: WW[p*100+k] = L[v, kix[k], p]
    for (int idx = tid; idx < KP*NK; idx += 256) {
        int p = idx / NK, k = idx % NK;
        WW[p*100 + k] = d_L[((size_t)v*LV + kix[k])*KP + p];
    }
    __syncthreads();
    // softmax over k per p (in place)
    if (tid < KP) {
        float m = -INFINITY;
        for (int k = 0; k < NK; k++) m = fmaxf(m, WW[tid*100 + k]);
        float Z = 0.f;
        for (int k = 0; k < NK; k++) { float e = expf(WW[tid*100 + k] - m); WW[tid*100 + k] = e; Z += e; }
        float iz = 1.f / Z;
        for (int k = 0; k < NK; k++) WW[tid*100 + k] *= iz;
    }
    __syncthreads();

    // aggr[p, c] = sum_k w[p,k] * S[k,c], tiled over c in chunks of 128
    for (int c0 = 0; c0 < CC; c0 += 128) {
        for (int idx = tid; idx < NK*32; idx += 256) {
            int r = idx >> 5, q = (idx & 31) << 2;
            *(float4*)&SC[r*132 + q] =
                *(const float4*)&img[((size_t)v*LV + kix[r])*CC + c0 + q];
        }
        __syncthreads();
        float acc[4][8];
        #pragma unroll
        for (int i = 0; i < 4; i++)
            #pragma unroll
            for (int j = 0; j < 8; j++) acc[i][j] = 0.f;
        #pragma unroll 2
        for (int k = 0; k < NK; k++) {
            float4 s0 = *(float4*)&SC[k*132 + (tx<<2)];
            float4 s1 = *(float4*)&SC[k*132 + 64 + (tx<<2)];
            float wv[4];
            #pragma unroll
            for (int i = 0; i < 4; i++) { int p = ty + 16*i; if (p > 48) p = 48; wv[i] = WW[p*100 + k]; }
            #pragma unroll
            for (int i = 0; i < 4; i++) {
                acc[i][0] += wv[i] * s0.x; acc[i][1] += wv[i] * s0.y;
                acc[i][2] += wv[i] * s0.z; acc[i][3] += wv[i] * s0.w;
                acc[i][4] += wv[i] * s1.x; acc[i][5] += wv[i] * s1.y;
                acc[i][6] += wv[i] * s1.z; acc[i][7] += wv[i] * s1.w;
            }
        }
        #pragma unroll
        for (int i = 0; i < 4; i++) {
            int p = ty + 16*i;
            if (p < KP) {
                float4 o0 = make_float4(acc[i][0], acc[i][1], acc[i][2], acc[i][3]);
                float4 o1 = make_float4(acc[i][4], acc[i][5], acc[i][6], acc[i][7]);
                *(float4*)&KT[p*520 + c0 + (tx<<2)] = o0;
                *(float4*)&KT[p*520 + c0 + 64 + (tx<<2)] = o1;
            }
        }
        __syncthreads();
    }

    // inverse l2 norms of all 50 keep_tokens
    for (int p = wid; p < KP + 1; p += 8) {
        float ss = 0.f;
        #pragma unroll
        for (int e = 0; e < 16; e++) { float x = KT[p*520 + lane + 32*e]; ss += x * x; }
        for (int o = 16; o; o >>= 1) ss += __shfl_xor_sync(0xffffffffu, ss, o);
        if (lane == 0) invn[p] = 1.f / fmaxf(sqrtf(ss), 1e-12f);
    }
    __syncthreads();

    // load normalized caption words into SC region
    for (int idx = tid; idx < NW*CC; idx += 256) {
        int w = idx >> 9, c = idx & 511;
        SC[w*516 + c] = cap[((size_t)t*NW + w)*CC + c] * d_capinv[t*NW + w];
    }
    __syncthreads();

    // per-word: sims -> softmax -> ctx -> word_sim (one warp per word)
    for (int w = wid; w < NW; w += 8) {
        for (int p = 0; p < KP + 1; p++) {
            float d = 0.f;
            #pragma unroll
            for (int e = 0; e < 16; e++) d += SC[w*516 + lane + 32*e] * KT[p*520 + lane + 32*e];
            for (int o = 16; o; o >>= 1) d += __shfl_xor_sync(0xffffffffu, d, o);
            if (lane == 0) ATT[w*52 + p] = 4.f * invn[p] * d;
        }
        __syncwarp();
        float a0 = (lane < 50) ? ATT[w*52 + lane] : -INFINITY;
        float a1 = (lane + 32 < 50) ? ATT[w*52 + lane + 32] : -INFINITY;
        float m = fmaxf(a0, a1);
        for (int o = 16; o; o >>= 1) m = fmaxf(m, __shfl_xor_sync(0xffffffffu, m, o));
        float e0 = (lane < 50) ? expf(a0 - m) : 0.f;
        float e1 = (lane + 32 < 50) ? expf(a1 - m) : 0.f;
        float Z = e0 + e1;
        for (int o = 16; o; o >>= 1) Z += __shfl_xor_sync(0xffffffffu, Z, o);
        float iz = 1.f / Z;
        if (lane < 50) ATT[w*52 + lane] = e0 * iz;
        if (lane + 32 < 50) ATT[w*52 + lane + 32] = e1 * iz;
        __syncwarp();
        float cx[16];
        #pragma unroll
        for (int e = 0; e < 16; e++) cx[e] = 0.f;
        for (int p = 0; p < KP + 1; p++) {
            float a = ATT[w*52 + p] * invn[p];
            #pragma unroll
            for (int e = 0; e < 16; e++) cx[e] += a * KT[p*520 + lane + 32*e];
        }
        float ss = 0.f, dt = 0.f;
        #pragma unroll
        for (int e = 0; e < 16; e++) {
            ss += cx[e] * cx[e];
            dt += cx[e] * SC[w*516 + lane + 32*e];
        }
        for (int o = 16; o; o >>= 1) {
            ss += __shfl_xor_sync(0xffffffffu, ss, o);
            dt += __shfl_xor_sync(0xffffffffu, dt, o);
        }
        if (lane == 0) wsm[w] = dt / fmaxf(sqrtf(ss), 1e-12f);
    }
    __syncthreads();
    if (tid == 0) {
        float s = 0.f;
        for (int w = 0; w < NW; w++) s += wsm[w];
        out[v*BT + t] = s / (float)NW;   // improve_sims = sim.T
    }
}

// ------------------------------ launch ----------------------------------
extern "C" void kernel_launch(void* const* d_in, const int* in_sizes, int n_in,
                              void* d_out, int out_size) {
    const float* img   = (const float*)d_in[0];
    const float* cap   = (const float*)d_in[1];
    // d_in[2] = cap_lens (unused by reference math)
    const float* gamma = (const float*)d_in[3];
    const float* beta  = (const float*)d_in[4];
    const float* W1    = (const float*)d_in[5];
    const float* b1    = (const float*)d_in[6];
    const float* W2    = (const float*)d_in[7];
    const float* b2    = (const float*)d_in[8];
    const float* scale = (const float*)d_in[9];
    float* out = (float*)d_out;

    kRowStats<<<BV*LV, 128>>>(img);
    kGloImg<<<BV, 512>>>(img);
    kGloCap<<<BT, 512>>>(cap);
    kCapRow<<<BT*NW, 128>>>(cap);
    kScore<<<dim3(LV, BV), 128>>>(img);
    kSelect<<<dim3(BT, BV), 256>>>(out);
    kExtra<<<BV, 256>>>(img);
    kPrepG1<<<(CC*HH + 255)/256, 256>>>(W1, gamma);
    kPrepCol<<<HH, 128>>>(W1, beta, b1);

    cudaFuncSetAttribute(kHL, cudaFuncAttributeMaxDynamicSharedMemorySize, SMEM_HL);
    kHL<<<dim3(BV, 2), 256, SMEM_HL>>>(img, W2, b2, scale);

    cudaFuncSetAttribute(kE2, cudaFuncAttributeMaxDynamicSharedMemorySize, SMEM_E2);
    kE2<<<dim3(BT, BV), 256, SMEM_E2>>>(img, cap, out);
}